// round 1
// baseline (speedup 1.0000x reference)
#include <cuda_runtime.h>

#define NB   2
#define NN   512
#define IND  512
#define MEMD 300
#define HIDD 64
#define NEG_SLOPE 0.01f

// ---------------- scratch (allocation-free: __device__ globals) -------------
__device__ float g_h[NB * NN * MEMD];      // per-layer node projection
__device__ float g_out1[NB * NN * MEMD];   // layer-1 output
__device__ float g_siT[NB * HIDD * NN];    // [b][h][i]  (transposed)
__device__ float g_sjT[NB * HIDD * NN];    // [b][h][j]  (transposed, +a1_b folded)
__device__ float g_p[NB * NN * NN];        // adj * exp(e)
__device__ float g_partial[NB * 64];       // per-block partial sums of p
__device__ float g_invZ[NB];               // 1/Z per batch

// ---------------- generic batched GEMM: C = scale * (A@B) + bias ------------
// A: (M,K) ld=K, B: (K,N) ld=N, C: (M,N) ld=N. grid.z = batch.
#define BM 32
#define BN 64
#define BK 16
__global__ void gemm_kernel(const float* __restrict__ A, long long sA,
                            const float* __restrict__ B, long long sB,
                            float* __restrict__ C, long long sC,
                            int M, int N, int K,
                            const float* __restrict__ bias,
                            const float* __restrict__ scale)
{
    int bz = blockIdx.z;
    A += (long long)bz * sA;
    B += (long long)bz * sB;
    C += (long long)bz * sC;

    __shared__ float As[BK][BM + 1];
    __shared__ float Bs[BK][BN + 1];

    int tx = threadIdx.x, ty = threadIdx.y;      // 16x16
    int tid = ty * 16 + tx;
    int row0 = blockIdx.y * BM;
    int col0 = blockIdx.x * BN;

    float acc[2][4] = {};

    for (int k0 = 0; k0 < K; k0 += BK) {
        // load A tile: BM*BK = 512 elems
        #pragma unroll
        for (int l = 0; l < (BM * BK) / 256; l++) {
            int idx = tid + l * 256;
            int m = idx / BK, kk = idx % BK;
            int k = k0 + kk, r = row0 + m;
            As[kk][m] = (k < K && r < M) ? A[(long long)r * K + k] : 0.f;
        }
        // load B tile: BK*BN = 1024 elems
        #pragma unroll
        for (int l = 0; l < (BK * BN) / 256; l++) {
            int idx = tid + l * 256;
            int kk = idx / BN, n = idx % BN;
            int k = k0 + kk, c = col0 + n;
            Bs[kk][n] = (k < K && c < N) ? B[(long long)k * N + c] : 0.f;
        }
        __syncthreads();

        #pragma unroll
        for (int kk = 0; kk < BK; kk++) {
            float a[2], b[4];
            #pragma unroll
            for (int i = 0; i < 2; i++) a[i] = As[kk][ty + 16 * i];
            #pragma unroll
            for (int j = 0; j < 4; j++) b[j] = Bs[kk][tx + 16 * j];
            #pragma unroll
            for (int i = 0; i < 2; i++)
                #pragma unroll
                for (int j = 0; j < 4; j++)
                    acc[i][j] += a[i] * b[j];
        }
        __syncthreads();
    }

    float sc = scale ? scale[bz] : 1.f;
    #pragma unroll
    for (int i = 0; i < 2; i++) {
        int r = row0 + ty + 16 * i;
        if (r >= M) continue;
        #pragma unroll
        for (int j = 0; j < 4; j++) {
            int c = col0 + tx + 16 * j;
            if (c >= N) continue;
            float v = acc[i][j] * sc;
            if (bias) v += bias[c];
            C[(long long)r * N + c] = v;
        }
    }
}

// ---------------- s projections: siT/sjT (transposed, bias folded) ----------
// one block per node row (b*512+i), 128 threads: 64 -> si, 64 -> sj
__global__ void s_kernel(const float* __restrict__ h,     // (1024, 300)
                         const float* __restrict__ a1w,   // (600, 64)
                         const float* __restrict__ a1b)   // (64)
{
    int row = blockIdx.x;           // 0..1023
    int t = threadIdx.x;            // 0..127
    __shared__ float hrow[MEMD];
    for (int k = t; k < MEMD; k += 128) hrow[k] = h[row * MEMD + k];
    __syncthreads();

    int hcol = t & 63;
    bool is_j = t >= 64;
    const float* w = a1w + (is_j ? MEMD * HIDD : 0);
    float acc = 0.f;
    #pragma unroll 4
    for (int k = 0; k < MEMD; k++)
        acc += hrow[k] * w[k * HIDD + hcol];

    int b = row >> 9, i = row & 511;
    if (is_j) {
        acc += a1b[hcol];
        g_sjT[(b * HIDD + hcol) * NN + i] = acc;
    } else {
        g_siT[(b * HIDD + hcol) * NN + i] = acc;
    }
}

// ---------------- pairwise e -> p = adj*exp(leaky_relu(e)) + partial Z ------
// block tile: 32 i x 128 j, 256 threads, 4x4 micro-tile per thread
#define TI 32
#define TJ 128
__global__ void pair_kernel(const float* __restrict__ a2w,
                            const float* __restrict__ a2b,
                            const float* __restrict__ adj)
{
    int b  = blockIdx.z;
    int i0 = blockIdx.y * TI;
    int j0 = blockIdx.x * TJ;

    __shared__ float Si[HIDD][TI + 1];
    __shared__ float Sj[HIDD][TJ + 1];
    __shared__ float W[HIDD];
    __shared__ float red[256];

    int tid = threadIdx.x;   // 256
    for (int idx = tid; idx < HIDD * TI; idx += 256) {
        int h = idx / TI, r = idx % TI;
        Si[h][r] = g_siT[(b * HIDD + h) * NN + i0 + r];
    }
    for (int idx = tid; idx < HIDD * TJ; idx += 256) {
        int h = idx / TJ, r = idx % TJ;
        Sj[h][r] = g_sjT[(b * HIDD + h) * NN + j0 + r];
    }
    if (tid < HIDD) W[tid] = a2w[tid];
    __syncthreads();

    int tx = tid & 31, ty = tid >> 5;   // ty 0..7

    float acc[4][4] = {};
    #pragma unroll 8
    for (int h = 0; h < HIDD; h++) {
        float w = W[h];
        float a[4], bb[4];
        #pragma unroll
        for (int ii = 0; ii < 4; ii++) a[ii] = Si[h][ty + 8 * ii];
        #pragma unroll
        for (int jj = 0; jj < 4; jj++) bb[jj] = Sj[h][tx + 32 * jj];
        #pragma unroll
        for (int ii = 0; ii < 4; ii++)
            #pragma unroll
            for (int jj = 0; jj < 4; jj++) {
                float x = a[ii] + bb[jj];
                acc[ii][jj] += fmaxf(x, 0.f) * w;
            }
    }

    float a2bv = a2b[0];
    float psum = 0.f;
    #pragma unroll
    for (int ii = 0; ii < 4; ii++) {
        int i = i0 + ty + 8 * ii;
        #pragma unroll
        for (int jj = 0; jj < 4; jj++) {
            int j = j0 + tx + 32 * jj;
            float e = acc[ii][jj] + a2bv;
            e = e > 0.f ? e : NEG_SLOPE * e;
            float ad = adj[((long long)b * NN + i) * NN + j];
            float pv = ad * __expf(e);
            g_p[((long long)b * NN + i) * NN + j] = pv;
            psum += pv;
        }
    }

    // deterministic block reduction
    red[tid] = psum;
    __syncthreads();
    for (int s = 128; s > 0; s >>= 1) {
        if (tid < s) red[tid] += red[tid + s];
        __syncthreads();
    }
    if (tid == 0)
        g_partial[b * 64 + blockIdx.y * gridDim.x + blockIdx.x] = red[0];
}

// ---------------- deterministic final Z reduction ---------------------------
__global__ void finalize_Z()
{
    int b = threadIdx.x;
    if (b < NB) {
        float s = 0.f;
        for (int k = 0; k < 64; k++) s += g_partial[b * 64 + k];
        g_invZ[b] = 1.f / s;
    }
}

// ---------------- host launcher ---------------------------------------------
extern "C" void kernel_launch(void* const* d_in, const int* in_sizes, int n_in,
                              void* d_out, int out_size)
{
    const float* feature = (const float*)d_in[0];
    const float* adj     = (const float*)d_in[1];
    const float* w0      = (const float*)d_in[2];
    const float* b0      = (const float*)d_in[3];
    const float* w1      = (const float*)d_in[4];
    const float* b1      = (const float*)d_in[5];
    const float* a1w     = (const float*)d_in[6];
    const float* a1b     = (const float*)d_in[7];
    const float* a2w     = (const float*)d_in[8];
    const float* a2b     = (const float*)d_in[9];
    float* out = (float*)d_out;

    float *ph, *pout1, *pp, *pinvZ;
    cudaGetSymbolAddress((void**)&ph,    g_h);
    cudaGetSymbolAddress((void**)&pout1, g_out1);
    cudaGetSymbolAddress((void**)&pp,    g_p);
    cudaGetSymbolAddress((void**)&pinvZ, g_invZ);

    dim3 thr(16, 16);
    dim3 grid_h((MEMD + BN - 1) / BN, (NB * NN) / BM, 1);    // (5, 32, 1)
    dim3 grid_o((MEMD + BN - 1) / BN, NN / BM, NB);          // (5, 16, 2)
    dim3 grid_pair(NN / TJ, NN / TI, NB);                    // (4, 16, 2)

    // ---------- layer 1 ----------
    gemm_kernel<<<grid_h, thr>>>(feature, 0, w0, 0, ph, 0,
                                 NB * NN, MEMD, IND, b0, nullptr);
    s_kernel<<<NB * NN, 128>>>(ph, a1w, a1b);
    pair_kernel<<<grid_pair, 256>>>(a2w, a2b, adj);
    finalize_Z<<<1, 32>>>();
    gemm_kernel<<<grid_o, thr>>>(pp, (long long)NN * NN,
                                 ph, (long long)NN * MEMD,
                                 pout1, (long long)NN * MEMD,
                                 NN, MEMD, NN, nullptr, pinvZ);

    // ---------- layer 2 ----------
    gemm_kernel<<<grid_h, thr>>>(pout1, 0, w1, 0, ph, 0,
                                 NB * NN, MEMD, MEMD, b1, nullptr);
    s_kernel<<<NB * NN, 128>>>(ph, a1w, a1b);
    pair_kernel<<<grid_pair, 256>>>(a2w, a2b, adj);
    finalize_Z<<<1, 32>>>();
    gemm_kernel<<<grid_o, thr>>>(pp, (long long)NN * NN,
                                 ph, (long long)NN * MEMD,
                                 out, (long long)NN * MEMD,
                                 NN, MEMD, NN, nullptr, pinvZ);
}

// round 2
// speedup vs baseline: 1.5304x; 1.5304x over previous
#include <cuda_runtime.h>

#define NB   2
#define NN   512
#define IND  512
#define MEMD 300
#define HIDD 64
#define NEG_SLOPE 0.01f

// ---------------- scratch (allocation-free: __device__ globals) -------------
__device__ float g_h[NB * NN * MEMD];      // per-layer node projection
__device__ float g_out1[NB * NN * MEMD];   // layer-1 output
__device__ float g_siT[NB * HIDD * NN];    // [b][h][i]  (transposed)
__device__ float g_sjT[NB * HIDD * NN];    // [b][h][j]  (transposed, +a1_b folded)
__device__ float g_p[NB * NN * NN];        // adj * exp(e)
__device__ float g_partial[NB * 64];       // per-block partial sums of p
__device__ float g_invZ[NB];               // 1/Z per batch

// ---------------- generic batched GEMM: C = scale * (A@B) + bias ------------
// A: (M,K) ld=K, B: (K,N) ld=N, C: (M,N) ld=N. grid.z = batch.
#define BM 32
#define BN 64
#define BK 16
__global__ void gemm_kernel(const float* __restrict__ A, long long sA,
                            const float* __restrict__ B, long long sB,
                            float* __restrict__ C, long long sC,
                            int M, int N, int K,
                            const float* __restrict__ bias,
                            const float* __restrict__ scale)
{
    int bz = blockIdx.z;
    A += (long long)bz * sA;
    B += (long long)bz * sB;
    C += (long long)bz * sC;

    __shared__ float As[BK][BM + 1];
    __shared__ float Bs[BK][BN + 1];

    int tx = threadIdx.x, ty = threadIdx.y;      // 16x16
    int tid = ty * 16 + tx;
    int row0 = blockIdx.y * BM;
    int col0 = blockIdx.x * BN;

    float acc[2][4] = {};

    for (int k0 = 0; k0 < K; k0 += BK) {
        // load A tile: BM*BK = 512 elems
        #pragma unroll
        for (int l = 0; l < (BM * BK) / 256; l++) {
            int idx = tid + l * 256;
            int m = idx / BK, kk = idx % BK;
            int k = k0 + kk, r = row0 + m;
            As[kk][m] = (k < K && r < M) ? A[(long long)r * K + k] : 0.f;
        }
        // load B tile: BK*BN = 1024 elems
        #pragma unroll
        for (int l = 0; l < (BK * BN) / 256; l++) {
            int idx = tid + l * 256;
            int kk = idx / BN, n = idx % BN;
            int k = k0 + kk, c = col0 + n;
            Bs[kk][n] = (k < K && c < N) ? B[(long long)k * N + c] : 0.f;
        }
        __syncthreads();

        #pragma unroll
        for (int kk = 0; kk < BK; kk++) {
            float a[2], b[4];
            #pragma unroll
            for (int i = 0; i < 2; i++) a[i] = As[kk][ty + 16 * i];
            #pragma unroll
            for (int j = 0; j < 4; j++) b[j] = Bs[kk][tx + 16 * j];
            #pragma unroll
            for (int i = 0; i < 2; i++)
                #pragma unroll
                for (int j = 0; j < 4; j++)
                    acc[i][j] += a[i] * b[j];
        }
        __syncthreads();
    }

    float sc = scale ? scale[bz] : 1.f;
    #pragma unroll
    for (int i = 0; i < 2; i++) {
        int r = row0 + ty + 16 * i;
        if (r >= M) continue;
        #pragma unroll
        for (int j = 0; j < 4; j++) {
            int c = col0 + tx + 16 * j;
            if (c >= N) continue;
            float v = acc[i][j] * sc;
            if (bias) v += bias[c];
            C[(long long)r * N + c] = v;
        }
    }
}

// ---------------- s projections: siT/sjT (transposed, bias folded) ----------
// one block per node row (b*512+i), 128 threads: 64 -> si, 64 -> sj
__global__ void s_kernel(const float* __restrict__ h,     // (1024, 300)
                         const float* __restrict__ a1w,   // (600, 64)
                         const float* __restrict__ a1b)   // (64)
{
    int row = blockIdx.x;           // 0..1023
    int t = threadIdx.x;            // 0..127
    __shared__ float hrow[MEMD];
    for (int k = t; k < MEMD; k += 128) hrow[k] = h[row * MEMD + k];
    __syncthreads();

    int hcol = t & 63;
    bool is_j = t >= 64;
    const float* w = a1w + (is_j ? MEMD * HIDD : 0);
    float acc = 0.f;
    #pragma unroll 4
    for (int k = 0; k < MEMD; k++)
        acc += hrow[k] * w[k * HIDD + hcol];

    int b = row >> 9, i = row & 511;
    if (is_j) {
        acc += a1b[hcol];
        g_sjT[(b * HIDD + hcol) * NN + i] = acc;
    } else {
        g_siT[(b * HIDD + hcol) * NN + i] = acc;
    }
}

// ---------------- pairwise e -> p = adj*exp(leaky_relu(e)) + partial Z ------
// block tile: 32 i x 128 j, 256 threads, 4x4 micro-tile per thread
#define TI 32
#define TJ 128
__global__ void pair_kernel(const float* __restrict__ a2w,
                            const float* __restrict__ a2b,
                            const float* __restrict__ adj)
{
    int b  = blockIdx.z;
    int i0 = blockIdx.y * TI;
    int j0 = blockIdx.x * TJ;

    __shared__ float Si[HIDD][TI + 1];
    __shared__ float Sj[HIDD][TJ + 1];
    __shared__ float W[HIDD];
    __shared__ float red[256];

    int tid = threadIdx.x;   // 256
    for (int idx = tid; idx < HIDD * TI; idx += 256) {
        int h = idx / TI, r = idx % TI;
        Si[h][r] = g_siT[(b * HIDD + h) * NN + i0 + r];
    }
    for (int idx = tid; idx < HIDD * TJ; idx += 256) {
        int h = idx / TJ, r = idx % TJ;
        Sj[h][r] = g_sjT[(b * HIDD + h) * NN + j0 + r];
    }
    if (tid < HIDD) W[tid] = a2w[tid];
    __syncthreads();

    int tx = tid & 31, ty = tid >> 5;   // ty 0..7

    float acc[4][4] = {};
    #pragma unroll 8
    for (int h = 0; h < HIDD; h++) {
        float w = W[h];
        float a[4], bb[4];
        #pragma unroll
        for (int ii = 0; ii < 4; ii++) a[ii] = Si[h][ty + 8 * ii];
        #pragma unroll
        for (int jj = 0; jj < 4; jj++) bb[jj] = Sj[h][tx + 32 * jj];
        #pragma unroll
        for (int ii = 0; ii < 4; ii++)
            #pragma unroll
            for (int jj = 0; jj < 4; jj++) {
                float x = a[ii] + bb[jj];
                acc[ii][jj] += fmaxf(x, 0.f) * w;
            }
    }

    float a2bv = a2b[0];
    float psum = 0.f;
    #pragma unroll
    for (int ii = 0; ii < 4; ii++) {
        int i = i0 + ty + 8 * ii;
        #pragma unroll
        for (int jj = 0; jj < 4; jj++) {
            int j = j0 + tx + 32 * jj;
            float e = acc[ii][jj] + a2bv;
            e = e > 0.f ? e : NEG_SLOPE * e;
            float ad = adj[((long long)b * NN + i) * NN + j];
            float pv = ad * __expf(e);
            g_p[((long long)b * NN + i) * NN + j] = pv;
            psum += pv;
        }
    }

    // deterministic block reduction
    red[tid] = psum;
    __syncthreads();
    for (int s = 128; s > 0; s >>= 1) {
        if (tid < s) red[tid] += red[tid + s];
        __syncthreads();
    }
    if (tid == 0)
        g_partial[b * 64 + blockIdx.y * gridDim.x + blockIdx.x] = red[0];
}

// ---------------- deterministic final Z reduction ---------------------------
__global__ void finalize_Z()
{
    int b = threadIdx.x;
    if (b < NB) {
        float s = 0.f;
        for (int k = 0; k < 64; k++) s += g_partial[b * 64 + k];
        g_invZ[b] = 1.f / s;
    }
}

// ---------------- host launcher ---------------------------------------------
extern "C" void kernel_launch(void* const* d_in, const int* in_sizes, int n_in,
                              void* d_out, int out_size)
{
    const float* feature = (const float*)d_in[0];
    const float* adj     = (const float*)d_in[1];
    const float* w0      = (const float*)d_in[2];
    const float* b0      = (const float*)d_in[3];
    const float* w1      = (const float*)d_in[4];
    const float* b1      = (const float*)d_in[5];
    const float* a1w     = (const float*)d_in[6];
    const float* a1b     = (const float*)d_in[7];
    const float* a2w     = (const float*)d_in[8];
    const float* a2b     = (const float*)d_in[9];
    float* out = (float*)d_out;

    float *ph, *pout1, *pp, *pinvZ;
    cudaGetSymbolAddress((void**)&ph,    g_h);
    cudaGetSymbolAddress((void**)&pout1, g_out1);
    cudaGetSymbolAddress((void**)&pp,    g_p);
    cudaGetSymbolAddress((void**)&pinvZ, g_invZ);

    dim3 thr(16, 16);
    dim3 grid_h((MEMD + BN - 1) / BN, (NB * NN) / BM, 1);    // (5, 32, 1)
    dim3 grid_o((MEMD + BN - 1) / BN, NN / BM, NB);          // (5, 16, 2)
    dim3 grid_pair(NN / TJ, NN / TI, NB);                    // (4, 16, 2)

    // ---------- layer 1 ----------
    gemm_kernel<<<grid_h, thr>>>(feature, 0, w0, 0, ph, 0,
                                 NB * NN, MEMD, IND, b0, nullptr);
    s_kernel<<<NB * NN, 128>>>(ph, a1w, a1b);
    pair_kernel<<<grid_pair, 256>>>(a2w, a2b, adj);
    finalize_Z<<<1, 32>>>();
    gemm_kernel<<<grid_o, thr>>>(pp, (long long)NN * NN,
                                 ph, (long long)NN * MEMD,
                                 pout1, (long long)NN * MEMD,
                                 NN, MEMD, NN, nullptr, pinvZ);

    // ---------- layer 2 ----------
    gemm_kernel<<<grid_h, thr>>>(pout1, 0, w1, 0, ph, 0,
                                 NB * NN, MEMD, MEMD, b1, nullptr);
    s_kernel<<<NB * NN, 128>>>(ph, a1w, a1b);
    pair_kernel<<<grid_pair, 256>>>(a2w, a2b, adj);
    finalize_Z<<<1, 32>>>();
    gemm_kernel<<<grid_o, thr>>>(pp, (long long)NN * NN,
                                 ph, (long long)NN * MEMD,
                                 out, (long long)NN * MEMD,
                                 NN, MEMD, NN, nullptr, pinvZ);
}